// round 4
// baseline (speedup 1.0000x reference)
#include <cuda_runtime.h>
#include <math.h>

typedef unsigned long long ull;

#define B_   64
#define T_   512
#define H_   1024
#define L_   2
#define G_   4096
#define K2_  2048
#define NBLK 128
#define SMEM_FLOATS 43520          // Ws 32768 + hs 2*4096 + gt 2048 + cs 512
#define SMEM_BYTES  (SMEM_FLOATS * 4)

__device__ float g_gin[(size_t)B_ * T_ * G_];
__device__ float g_mid[(size_t)B_ * T_ * H_];
__device__ float g_hT[2][H_ * B_];
__device__ unsigned g_cnt = 0;
__device__ unsigned g_gen = 0;

__device__ __forceinline__ void ffma2(ull& d, ull a, ull b) {
    asm volatile("fma.rn.f32x2 %0, %1, %2, %0;" : "+l"(d) : "l"(a), "l"(b));
}
__device__ __forceinline__ ull dup2(float x) {
    ull r; asm("mov.b64 %0, {%1, %1};" : "=l"(r) : "f"(x)); return r;
}
__device__ __forceinline__ float2 unpack2(ull v) {
    float2 f; asm("mov.b64 {%0, %1}, %2;" : "=f"(f.x), "=f"(f.y) : "l"(v)); return f;
}
__device__ __forceinline__ float sigmoidf_(float x) { return 1.0f / (1.0f + expf(-x)); }

__device__ __forceinline__ void cp_async16(const float* smem_dst, const float* gsrc) {
    unsigned sa = (unsigned)__cvta_generic_to_shared((void*)smem_dst);
    asm volatile("cp.async.cg.shared.global [%0], [%1], 16;" :: "r"(sa), "l"(gsrc));
}

__device__ __forceinline__ void grid_barrier() {
    __syncthreads();
    if (threadIdx.x == 0) {
        __threadfence();
        unsigned old;
        asm volatile("ld.relaxed.gpu.u32 %0, [%1];" : "=r"(old) : "l"(&g_gen));
        if (atomicAdd(&g_cnt, 1u) == NBLK - 1) {
            asm volatile("st.relaxed.gpu.u32 [%0], %1;" :: "l"(&g_cnt), "r"(0u));
            asm volatile("st.release.gpu.u32 [%0], %1;" :: "l"(&g_gen), "r"(old + 1u));
        } else {
            unsigned cur;
            do {
                __nanosleep(32);
                asm volatile("ld.acquire.gpu.u32 %0, [%1];" : "=r"(cur) : "l"(&g_gen));
            } while (cur == old);
        }
    }
    __syncthreads();
}

// ---------------------------------------------------------------------------
// h0 transpose: hT[k*64 + b] = h0l[b*H + k]
// ---------------------------------------------------------------------------
__global__ void h0_transpose(const float* __restrict__ h0l, float* __restrict__ hT) {
    int idx = blockIdx.x * 256 + threadIdx.x;
    int b = idx & 63, k = idx >> 6;
    hT[idx] = h0l[b * H_ + k];
}

// ---------------------------------------------------------------------------
// Input GEMM: gin[m, n] = A[m, 0:H] . W[n, 0:H] + bias[n]
// 128(M) x 64(N) tile, BK=16, 256 threads, thread tile 8m x 4n (f32x2 packed)
// ---------------------------------------------------------------------------
__global__ void __launch_bounds__(256) lstm_in_gemm(
    const float* __restrict__ A, const float* __restrict__ Wl,
    const float* __restrict__ bl, float* __restrict__ C)
{
    __shared__ float  As[16][128];
    __shared__ float2 Bs[16][2][16][2];   // [kk][h][tx][e] : dup pair for n = tx*4+2h+e

    const int tid = threadIdx.x;
    const int n0 = blockIdx.x * 64;
    const int m0 = blockIdx.y * 128;

    const int ar = tid >> 1, ac = (tid & 1) * 8;
    const float* aptr = A + (size_t)(m0 + ar) * H_ + ac;
    const int wr = tid & 63, wc = (tid >> 6) * 4;
    const float* wptr = Wl + (size_t)(n0 + wr) * K2_ + wc;
    const int btx = wr >> 2, bh = (wr >> 1) & 1, be = wr & 1;

    const int tx = tid & 15, ty = tid >> 4;

    ull acc[4][4];
#pragma unroll
    for (int i = 0; i < 4; i++)
#pragma unroll
        for (int j = 0; j < 4; j++) acc[i][j] = 0ULL;

    float4 a0 = *(const float4*)aptr;
    float4 a1 = *(const float4*)(aptr + 4);
    float4 w0 = *(const float4*)wptr;

    for (int k0 = 0; k0 < H_; k0 += 16) {
        As[ac + 0][ar] = a0.x; As[ac + 1][ar] = a0.y;
        As[ac + 2][ar] = a0.z; As[ac + 3][ar] = a0.w;
        As[ac + 4][ar] = a1.x; As[ac + 5][ar] = a1.y;
        As[ac + 6][ar] = a1.z; As[ac + 7][ar] = a1.w;
        Bs[wc + 0][bh][btx][be] = make_float2(w0.x, w0.x);
        Bs[wc + 1][bh][btx][be] = make_float2(w0.y, w0.y);
        Bs[wc + 2][bh][btx][be] = make_float2(w0.z, w0.z);
        Bs[wc + 3][bh][btx][be] = make_float2(w0.w, w0.w);
        __syncthreads();

        if (k0 + 16 < H_) {
            a0 = *(const float4*)(aptr + k0 + 16);
            a1 = *(const float4*)(aptr + k0 + 20);
            w0 = *(const float4*)(wptr + k0 + 16);
        }

#pragma unroll
        for (int kk = 0; kk < 16; kk++) {
            ulonglong2 aL = *(const ulonglong2*)&As[kk][ty * 8];
            ulonglong2 aH = *(const ulonglong2*)&As[kk][ty * 8 + 4];
            ulonglong2 b0 = *(const ulonglong2*)&Bs[kk][0][tx][0];
            ulonglong2 b1 = *(const ulonglong2*)&Bs[kk][1][tx][0];
            ffma2(acc[0][0], aL.x, b0.x); ffma2(acc[0][1], aL.x, b0.y);
            ffma2(acc[0][2], aL.x, b1.x); ffma2(acc[0][3], aL.x, b1.y);
            ffma2(acc[1][0], aL.y, b0.x); ffma2(acc[1][1], aL.y, b0.y);
            ffma2(acc[1][2], aL.y, b1.x); ffma2(acc[1][3], aL.y, b1.y);
            ffma2(acc[2][0], aH.x, b0.x); ffma2(acc[2][1], aH.x, b0.y);
            ffma2(acc[2][2], aH.x, b1.x); ffma2(acc[2][3], aH.x, b1.y);
            ffma2(acc[3][0], aH.y, b0.x); ffma2(acc[3][1], aH.y, b0.y);
            ffma2(acc[3][2], aH.y, b1.x); ffma2(acc[3][3], aH.y, b1.y);
        }
        __syncthreads();
    }

    float4 bias = *(const float4*)&bl[n0 + tx * 4];
#pragma unroll
    for (int mi = 0; mi < 4; mi++) {
        float2 c0 = unpack2(acc[mi][0]);
        float2 c1 = unpack2(acc[mi][1]);
        float2 c2 = unpack2(acc[mi][2]);
        float2 c3 = unpack2(acc[mi][3]);
        size_t r = (size_t)(m0 + ty * 8 + 2 * mi) * G_ + n0 + tx * 4;
        *(float4*)&C[r] = make_float4(c0.x + bias.x, c1.x + bias.y,
                                      c2.x + bias.z, c3.x + bias.w);
        *(float4*)&C[r + G_] = make_float4(c0.y + bias.x, c1.y + bias.y,
                                           c2.y + bias.z, c3.y + bias.w);
    }
}

// ---------------------------------------------------------------------------
// Persistent recurrent kernel: one launch per layer, 512 steps, grid barrier.
// Block jb owns gate columns {gate*H + jb*8 + jj} (32 cols), W slice in smem.
// ---------------------------------------------------------------------------
__global__ void __launch_bounds__(128, 1) lstm_seq(
    const float* __restrict__ Wl, const float* __restrict__ gin,
    const float* __restrict__ c0l, float* __restrict__ hT0,
    float* __restrict__ hT1, float* __restrict__ layer_out,
    float* __restrict__ outp, int l)
{
    extern __shared__ float sm[];
    float* Ws  = sm;              // 32768 floats: float4 at (k2*16 + col2)
    float* hsA = sm + 32768;      // 4096: h tile [kk][b]
    float* hsB = sm + 36864;      // 4096
    float* gt  = sm + 40960;      // 2048: [col][64]
    float* cs  = sm + 43008;      // 512:  [b*8 + jj]

    const int tid = threadIdx.x;
    const int jb  = blockIdx.x;
    const int lane = tid & 31, warp = tid >> 5;
    const int col2 = lane & 15, msel = lane >> 4;
    const int m_base = warp * 16 + msel * 8;

    // --- Ws fill (once per layer): Ws4[k2*16+col2] = {w(2k2,c0), w(2k2,c1), w(2k2+1,c0), w(2k2+1,c1)}
    {
        const int cf = tid >> 3;               // 0..15
        const int c0 = 2 * cf, c1 = c0 + 1;
        const int gr0 = (c0 >> 3) * H_ + jb * 8 + (c0 & 7);
        const int gr1 = (c1 >> 3) * H_ + jb * 8 + (c1 & 7);
        const float* r0 = Wl + (size_t)gr0 * K2_ + H_;
        const float* r1 = Wl + (size_t)gr1 * K2_ + H_;
        const int k2s = (tid & 7) * 64;
        for (int q = 0; q < 64; q++) {
            int k2 = k2s + q;
            float2 va = *(const float2*)(r0 + 2 * k2);
            float2 vb = *(const float2*)(r1 + 2 * k2);
            ((float4*)Ws)[k2 * 16 + cf] = make_float4(va.x, vb.x, va.y, vb.y);
        }
    }
    for (int i = tid; i < 512; i += 128)
        cs[i] = c0l[(i >> 3) * H_ + jb * 8 + (i & 7)];
    __syncthreads();

    const int b_pw = tid >> 1;
    const int jj0 = (tid & 1) * 4;

    for (int t = 0; t < T_; t++) {
        const float* hTr = (t & 1) ? hT1 : hT0;
        float*       hTw = (t & 1) ? hT0 : hT1;

        grid_barrier();

        const float* gp = gin + ((size_t)b_pw * T_ + t) * G_ + jb * 8 + jj0;
        float4 pf = __ldg((const float4*)gp);
        float4 pi = __ldg((const float4*)(gp + H_));
        float4 pg = __ldg((const float4*)(gp + 2 * H_));
        float4 po = __ldg((const float4*)(gp + 3 * H_));

        ull acc[8];
#pragma unroll
        for (int i = 0; i < 8; i++) acc[i] = 0ULL;

        // stage tile 0
#pragma unroll
        for (int w = 0; w < 8; w++)
            cp_async16(hsA + (tid + w * 128) * 4, hTr + (tid + w * 128) * 4);
        asm volatile("cp.async.commit_group;");

        for (int kt = 0; kt < 16; kt++) {
            float* hcur = (kt & 1) ? hsB : hsA;
            float* hnxt = (kt & 1) ? hsA : hsB;
            if (kt < 15) {
                const float* src = hTr + (kt + 1) * 4096;
#pragma unroll
                for (int w = 0; w < 8; w++)
                    cp_async16(hnxt + (tid + w * 128) * 4, src + (tid + w * 128) * 4);
                asm volatile("cp.async.commit_group;");
                asm volatile("cp.async.wait_group 1;");
            } else {
                asm volatile("cp.async.wait_group 0;");
            }
            __syncthreads();

            const float4* Wv = (const float4*)Ws + kt * 32 * 16;
#pragma unroll 8
            for (int kk2 = 0; kk2 < 32; kk2++) {
                float4 w = Wv[kk2 * 16 + col2];
                ull w00 = dup2(w.x), w01 = dup2(w.y);
                ull w10 = dup2(w.z), w11 = dup2(w.w);
                const float* hr = hcur + (2 * kk2) * 64 + m_base;
                ulonglong2 aL0 = *(const ulonglong2*)hr;
                ulonglong2 aH0 = *(const ulonglong2*)(hr + 4);
                ulonglong2 aL1 = *(const ulonglong2*)(hr + 64);
                ulonglong2 aH1 = *(const ulonglong2*)(hr + 68);
                ffma2(acc[0], aL0.x, w00); ffma2(acc[1], aL0.x, w01);
                ffma2(acc[2], aL0.y, w00); ffma2(acc[3], aL0.y, w01);
                ffma2(acc[4], aH0.x, w00); ffma2(acc[5], aH0.x, w01);
                ffma2(acc[6], aH0.y, w00); ffma2(acc[7], aH0.y, w01);
                ffma2(acc[0], aL1.x, w10); ffma2(acc[1], aL1.x, w11);
                ffma2(acc[2], aL1.y, w10); ffma2(acc[3], aL1.y, w11);
                ffma2(acc[4], aH1.x, w10); ffma2(acc[5], aH1.x, w11);
                ffma2(acc[6], aH1.y, w10); ffma2(acc[7], aH1.y, w11);
            }
            __syncthreads();
        }

        // gates -> smem exchange
#pragma unroll
        for (int mi = 0; mi < 4; mi++) {
            float2 v0 = unpack2(acc[mi * 2 + 0]);
            float2 v1 = unpack2(acc[mi * 2 + 1]);
            *(float2*)&gt[(2 * col2 + 0) * 64 + m_base + 2 * mi] = v0;
            *(float2*)&gt[(2 * col2 + 1) * 64 + m_base + 2 * mi] = v1;
        }
        __syncthreads();

        // pointwise LSTM update (thread: batch b_pw, jj0..jj0+3)
        float4 cold = *(float4*)&cs[b_pw * 8 + jj0];
        float co[4] = {cold.x, cold.y, cold.z, cold.w};
        float pfv[4] = {pf.x, pf.y, pf.z, pf.w};
        float piv[4] = {pi.x, pi.y, pi.z, pi.w};
        float pgv[4] = {pg.x, pg.y, pg.z, pg.w};
        float pov[4] = {po.x, po.y, po.z, po.w};
        float hv[4], cv[4];
#pragma unroll
        for (int j = 0; j < 4; j++) {
            int jj = jj0 + j;
            float xf = gt[jj * 64 + b_pw]        + pfv[j];
            float xi = gt[(8 + jj) * 64 + b_pw]  + piv[j];
            float xg = gt[(16 + jj) * 64 + b_pw] + pgv[j];
            float xo = gt[(24 + jj) * 64 + b_pw] + pov[j];
            float f = sigmoidf_(xf), ig = sigmoidf_(xi);
            float g = tanhf(xg),     o  = sigmoidf_(xo);
            cv[j] = f * co[j] + ig * g;
            hv[j] = o * tanhf(cv[j]);
        }
        *(float4*)&cs[b_pw * 8 + jj0] = make_float4(cv[0], cv[1], cv[2], cv[3]);
#pragma unroll
        for (int j = 0; j < 4; j++)
            hTw[(jb * 8 + jj0 + j) * 64 + b_pw] = hv[j];
        *(float4*)&layer_out[((size_t)b_pw * T_ + t) * H_ + jb * 8 + jj0] =
            make_float4(hv[0], hv[1], hv[2], hv[3]);
        if (t == T_ - 1) {
            size_t hb = (size_t)B_ * T_ * H_ + (size_t)l * B_ * H_ +
                        (size_t)b_pw * H_ + jb * 8 + jj0;
            *(float4*)&outp[hb] = make_float4(hv[0], hv[1], hv[2], hv[3]);
            *(float4*)&outp[hb + (size_t)L_ * B_ * H_] =
                make_float4(cv[0], cv[1], cv[2], cv[3]);
        }
    }
}

extern "C" void kernel_launch(void* const* d_in, const int* in_sizes, int n_in,
                              void* d_out, int out_size)
{
    const float* x  = (const float*)d_in[0];
    const float* W  = (const float*)d_in[1];
    const float* bs = (const float*)d_in[2];
    const float* h0 = (const float*)d_in[3];
    const float* c0 = (const float*)d_in[4];
    float* out = (float*)d_out;

    float *gin, *mid, *hT;
    cudaGetSymbolAddress((void**)&gin, g_gin);
    cudaGetSymbolAddress((void**)&mid, g_mid);
    cudaGetSymbolAddress((void**)&hT, g_hT);
    float* hT0 = hT;
    float* hT1 = hT + H_ * B_;

    cudaFuncSetAttribute(lstm_seq, cudaFuncAttributeMaxDynamicSharedMemorySize,
                         SMEM_BYTES);

    for (int l = 0; l < L_; l++) {
        const float* layer_in  = (l == 0) ? x   : mid;
        float*       layer_out = (l == 0) ? mid : out;
        const float* Wl = W  + (size_t)l * G_ * K2_;
        const float* bl = bs + (size_t)l * G_;

        h0_transpose<<<256, 256>>>(h0 + (size_t)l * B_ * H_, hT0);
        lstm_in_gemm<<<dim3(64, 256), 256>>>(layer_in, Wl, bl, gin);
        lstm_seq<<<NBLK, 128, SMEM_BYTES>>>(Wl, gin, c0 + (size_t)l * B_ * H_,
                                            hT0, hT1, layer_out, out, l);
    }
}

// round 5
// speedup vs baseline: 1.0357x; 1.0357x over previous
#include <cuda_runtime.h>
#include <math.h>

typedef unsigned long long ull;

#define B_   64
#define T_   512
#define H_   1024
#define L_   2
#define G_   4096
#define K2_  2048
#define NBLK 128

// smem plan (floats): Ws 32768 | hsA 4096 | hsB 4096 | gt 2*32*66=4224 | cs 512
#define WS_OFF   0
#define HSA_OFF  32768
#define HSB_OFF  36864
#define GT_OFF   40960
#define GT_GRP   2112            // 32*66
#define CS_OFF   45184
#define SMEM_FLOATS 45696
#define SMEM_BYTES  (SMEM_FLOATS * 4)

__device__ float g_gin[(size_t)B_ * T_ * G_];
__device__ float g_mid[(size_t)B_ * T_ * H_];
__device__ float g_hT[2][H_ * B_];
__device__ unsigned g_cnt = 0;
__device__ unsigned g_gen = 0;

__device__ __forceinline__ void ffma2(ull& d, ull a, ull b) {
    asm volatile("fma.rn.f32x2 %0, %1, %2, %0;" : "+l"(d) : "l"(a), "l"(b));
}
__device__ __forceinline__ ull dup2(float x) {
    ull r; asm("mov.b64 %0, {%1, %1};" : "=l"(r) : "f"(x)); return r;
}
__device__ __forceinline__ float2 unpack2(ull v) {
    float2 f; asm("mov.b64 {%0, %1}, %2;" : "=f"(f.x), "=f"(f.y) : "l"(v)); return f;
}
__device__ __forceinline__ float sigmoidf_(float x) {
    return __fdividef(1.0f, 1.0f + expf(-x));
}
__device__ __forceinline__ void cp_async16(const float* smem_dst, const float* gsrc) {
    unsigned sa = (unsigned)__cvta_generic_to_shared((void*)smem_dst);
    asm volatile("cp.async.cg.shared.global [%0], [%1], 16;" :: "r"(sa), "l"(gsrc));
}

__device__ __forceinline__ void grid_barrier() {
    __syncthreads();
    if (threadIdx.x == 0) {
        asm volatile("fence.acq_rel.gpu;" ::: "memory");
        unsigned old;
        asm volatile("ld.relaxed.gpu.u32 %0, [%1];" : "=r"(old) : "l"(&g_gen));
        if (atomicAdd(&g_cnt, 1u) == NBLK - 1) {
            asm volatile("st.relaxed.gpu.u32 [%0], %1;" :: "l"(&g_cnt), "r"(0u));
            asm volatile("st.release.gpu.u32 [%0], %1;" :: "l"(&g_gen), "r"(old + 1u));
        } else {
            unsigned cur;
            do {
                asm volatile("ld.acquire.gpu.u32 %0, [%1];" : "=r"(cur) : "l"(&g_gen));
            } while (cur == old);
        }
    }
    __syncthreads();
}

// ---------------------------------------------------------------------------
// h0 transpose: hT[k*64 + b] = h0l[b*H + k]
// ---------------------------------------------------------------------------
__global__ void h0_transpose(const float* __restrict__ h0l, float* __restrict__ hT) {
    int idx = blockIdx.x * 256 + threadIdx.x;
    int b = idx & 63, k = idx >> 6;
    hT[idx] = h0l[b * H_ + k];
}

// ---------------------------------------------------------------------------
// Input GEMM: gin[m, n] = A[m, 0:H] . W[n, 0:H] + bias[n]
// 128(M) x 64(N) tile, BK=16, 256 threads, thread tile 8m x 4n (f32x2 packed)
// (unchanged from R3 — near its FFMA2 floor by model; revisit with tcgen05)
// ---------------------------------------------------------------------------
__global__ void __launch_bounds__(256) lstm_in_gemm(
    const float* __restrict__ A, const float* __restrict__ Wl,
    const float* __restrict__ bl, float* __restrict__ C)
{
    __shared__ float  As[16][128];
    __shared__ float2 Bs[16][2][16][2];

    const int tid = threadIdx.x;
    const int n0 = blockIdx.x * 64;
    const int m0 = blockIdx.y * 128;

    const int ar = tid >> 1, ac = (tid & 1) * 8;
    const float* aptr = A + (size_t)(m0 + ar) * H_ + ac;
    const int wr = tid & 63, wc = (tid >> 6) * 4;
    const float* wptr = Wl + (size_t)(n0 + wr) * K2_ + wc;
    const int btx = wr >> 2, bh = (wr >> 1) & 1, be = wr & 1;

    const int tx = tid & 15, ty = tid >> 4;

    ull acc[4][4];
#pragma unroll
    for (int i = 0; i < 4; i++)
#pragma unroll
        for (int j = 0; j < 4; j++) acc[i][j] = 0ULL;

    float4 a0 = *(const float4*)aptr;
    float4 a1 = *(const float4*)(aptr + 4);
    float4 w0 = *(const float4*)wptr;

    for (int k0 = 0; k0 < H_; k0 += 16) {
        As[ac + 0][ar] = a0.x; As[ac + 1][ar] = a0.y;
        As[ac + 2][ar] = a0.z; As[ac + 3][ar] = a0.w;
        As[ac + 4][ar] = a1.x; As[ac + 5][ar] = a1.y;
        As[ac + 6][ar] = a1.z; As[ac + 7][ar] = a1.w;
        Bs[wc + 0][bh][btx][be] = make_float2(w0.x, w0.x);
        Bs[wc + 1][bh][btx][be] = make_float2(w0.y, w0.y);
        Bs[wc + 2][bh][btx][be] = make_float2(w0.z, w0.z);
        Bs[wc + 3][bh][btx][be] = make_float2(w0.w, w0.w);
        __syncthreads();

        if (k0 + 16 < H_) {
            a0 = *(const float4*)(aptr + k0 + 16);
            a1 = *(const float4*)(aptr + k0 + 20);
            w0 = *(const float4*)(wptr + k0 + 16);
        }

#pragma unroll
        for (int kk = 0; kk < 16; kk++) {
            ulonglong2 aL = *(const ulonglong2*)&As[kk][ty * 8];
            ulonglong2 aH = *(const ulonglong2*)&As[kk][ty * 8 + 4];
            ulonglong2 b0 = *(const ulonglong2*)&Bs[kk][0][tx][0];
            ulonglong2 b1 = *(const ulonglong2*)&Bs[kk][1][tx][0];
            ffma2(acc[0][0], aL.x, b0.x); ffma2(acc[0][1], aL.x, b0.y);
            ffma2(acc[0][2], aL.x, b1.x); ffma2(acc[0][3], aL.x, b1.y);
            ffma2(acc[1][0], aL.y, b0.x); ffma2(acc[1][1], aL.y, b0.y);
            ffma2(acc[1][2], aL.y, b1.x); ffma2(acc[1][3], aL.y, b1.y);
            ffma2(acc[2][0], aH.x, b0.x); ffma2(acc[2][1], aH.x, b0.y);
            ffma2(acc[2][2], aH.x, b1.x); ffma2(acc[2][3], aH.x, b1.y);
            ffma2(acc[3][0], aH.y, b0.x); ffma2(acc[3][1], aH.y, b0.y);
            ffma2(acc[3][2], aH.y, b1.x); ffma2(acc[3][3], aH.y, b1.y);
        }
        __syncthreads();
    }

    float4 bias = *(const float4*)&bl[n0 + tx * 4];
#pragma unroll
    for (int mi = 0; mi < 4; mi++) {
        float2 c0 = unpack2(acc[mi][0]);
        float2 c1 = unpack2(acc[mi][1]);
        float2 c2 = unpack2(acc[mi][2]);
        float2 c3 = unpack2(acc[mi][3]);
        size_t r = (size_t)(m0 + ty * 8 + 2 * mi) * G_ + n0 + tx * 4;
        *(float4*)&C[r] = make_float4(c0.x + bias.x, c1.x + bias.y,
                                      c2.x + bias.z, c3.x + bias.w);
        *(float4*)&C[r + G_] = make_float4(c0.y + bias.x, c1.y + bias.y,
                                           c2.y + bias.z, c3.y + bias.w);
    }
}

// ---------------------------------------------------------------------------
// Persistent recurrent kernel, 256 threads, k-split across 2 warp-groups.
// Block jb owns gate cols {g*H + jb*8 + jj : g<4, jj<8}; W slice in smem.
// Group 0: k in [0,512) (local kk2 0..15 of each 64-k tile); group 1: rest.
// ---------------------------------------------------------------------------
__global__ void __launch_bounds__(256, 1) lstm_seq(
    const float* __restrict__ Wl, const float* __restrict__ gin,
    const float* __restrict__ c0l, float* __restrict__ hT0,
    float* __restrict__ hT1, float* __restrict__ layer_out,
    float* __restrict__ outp, int l)
{
    extern __shared__ float sm[];
    float* Ws  = sm + WS_OFF;
    float* hsA = sm + HSA_OFF;
    float* hsB = sm + HSB_OFF;
    float* gt  = sm + GT_OFF;    // [grp][col stride 66][64 b]
    float* cs  = sm + CS_OFF;    // [b*8 + jj]

    const int tid = threadIdx.x;
    const int jb  = blockIdx.x;
    const int lane = tid & 31, warp = tid >> 5;
    const int grp  = warp >> 2;          // k-split group
    const int w4   = warp & 3;
    const int col2 = lane & 15;          // col pair: cols (2c, 2c+1)
    const int msel = lane >> 4;
    const int m_base = w4 * 16 + msel * 8;

    // --- Ws fill (once per layer): Ws4[k2*16+cf] = {w(2k2,c0), w(2k2,c1), w(2k2+1,c0), w(2k2+1,c1)}
    {
        const int cf = tid & 15;
        const int c0 = 2 * cf, c1 = c0 + 1;
        const int gr0 = (c0 >> 3) * H_ + jb * 8 + (c0 & 7);
        const int gr1 = (c1 >> 3) * H_ + jb * 8 + (c1 & 7);
        const float* r0 = Wl + (size_t)gr0 * K2_ + H_;
        const float* r1 = Wl + (size_t)gr1 * K2_ + H_;
        const int k2s = (tid >> 4) * 32;
        for (int q = 0; q < 32; q++) {
            int k2 = k2s + q;
            float2 va = *(const float2*)(r0 + 2 * k2);
            float2 vb = *(const float2*)(r1 + 2 * k2);
            ((float4*)Ws)[k2 * 16 + cf] = make_float4(va.x, vb.x, va.y, vb.y);
        }
    }
    for (int i = tid; i < 512; i += 256)
        cs[i] = c0l[(i >> 3) * H_ + jb * 8 + (i & 7)];
    __syncthreads();

    const int b_pw = tid & 63;
    const int jj0  = (tid >> 6) * 2;     // 0,2,4,6

    for (int t = 0; t < T_; t++) {
        const float* hTr = (t & 1) ? hT1 : hT0;
        float*       hTw = (t & 1) ? hT0 : hT1;

        // gin prefetch (independent of h) — issue before the barrier
        const float* gp = gin + ((size_t)b_pw * T_ + t) * G_ + jb * 8 + jj0;
        float2 pf = __ldg((const float2*)gp);
        float2 pi = __ldg((const float2*)(gp + H_));
        float2 pg = __ldg((const float2*)(gp + 2 * H_));
        float2 po = __ldg((const float2*)(gp + 3 * H_));

        grid_barrier();

        // stage tile 0 (64 k x 64 b = 16KB)
#pragma unroll
        for (int w = 0; w < 4; w++)
            cp_async16(hsA + (tid + w * 256) * 4, hTr + (tid + w * 256) * 4);
        asm volatile("cp.async.commit_group;");

        ull acc[8];
#pragma unroll
        for (int i = 0; i < 8; i++) acc[i] = 0ULL;

        for (int kt = 0; kt < 16; kt++) {
            float* hcur = (kt & 1) ? hsB : hsA;
            float* hnxt = (kt & 1) ? hsA : hsB;
            if (kt < 15) {
                const float* src = hTr + (kt + 1) * 4096;
#pragma unroll
                for (int w = 0; w < 4; w++)
                    cp_async16(hnxt + (tid + w * 256) * 4, src + (tid + w * 256) * 4);
                asm volatile("cp.async.commit_group;");
                asm volatile("cp.async.wait_group 1;");
            } else {
                asm volatile("cp.async.wait_group 0;");
            }
            __syncthreads();

            const float4* Wv = (const float4*)Ws + (size_t)(kt * 32 + grp * 16) * 16;
            const float*  hb = hcur + grp * 32 * 64;
#pragma unroll
            for (int kk = 0; kk < 16; kk++) {
                float4 w = Wv[kk * 16 + col2];
                ull w00 = dup2(w.x), w01 = dup2(w.y);
                ull w10 = dup2(w.z), w11 = dup2(w.w);
                const float* hr = hb + (2 * kk) * 64 + m_base;
                ulonglong2 aL0 = *(const ulonglong2*)hr;
                ulonglong2 aH0 = *(const ulonglong2*)(hr + 4);
                ulonglong2 aL1 = *(const ulonglong2*)(hr + 64);
                ulonglong2 aH1 = *(const ulonglong2*)(hr + 68);
                ffma2(acc[0], aL0.x, w00); ffma2(acc[1], aL0.x, w01);
                ffma2(acc[2], aL0.y, w00); ffma2(acc[3], aL0.y, w01);
                ffma2(acc[4], aH0.x, w00); ffma2(acc[5], aH0.x, w01);
                ffma2(acc[6], aH0.y, w00); ffma2(acc[7], aH0.y, w01);
                ffma2(acc[0], aL1.x, w10); ffma2(acc[1], aL1.x, w11);
                ffma2(acc[2], aL1.y, w10); ffma2(acc[3], aL1.y, w11);
                ffma2(acc[4], aH1.x, w10); ffma2(acc[5], aH1.x, w11);
                ffma2(acc[6], aH1.y, w10); ffma2(acc[7], aH1.y, w11);
            }
            __syncthreads();
        }

        // partial gates -> smem (per group slab; stride 66 kills bank conflicts)
        float* gslab = gt + grp * GT_GRP;
#pragma unroll
        for (int mi = 0; mi < 4; mi++) {
            float2 v0 = unpack2(acc[mi * 2 + 0]);   // col 2*col2, rows m_base+2mi..+1
            float2 v1 = unpack2(acc[mi * 2 + 1]);   // col 2*col2+1
            *(float2*)&gslab[(2 * col2 + 0) * 66 + m_base + 2 * mi] = v0;
            *(float2*)&gslab[(2 * col2 + 1) * 66 + m_base + 2 * mi] = v1;
        }
        __syncthreads();

        // pointwise: thread owns batch b_pw, cols jj0, jj0+1
        float2 c_old = *(float2*)&cs[b_pw * 8 + jj0];
        float co[2] = {c_old.x, c_old.y};
        float gf[2] = {pf.x, pf.y}, gi2[2] = {pi.x, pi.y};
        float gg[2] = {pg.x, pg.y}, go[2] = {po.x, po.y};
        float hv[2], cv[2];
#pragma unroll
        for (int j = 0; j < 2; j++) {
            const int jj = jj0 + j;
            float xf = gt[jj * 66 + b_pw]        + gt[GT_GRP + jj * 66 + b_pw]        + gf[j];
            float xi = gt[(8 + jj) * 66 + b_pw]  + gt[GT_GRP + (8 + jj) * 66 + b_pw]  + gi2[j];
            float xg = gt[(16 + jj) * 66 + b_pw] + gt[GT_GRP + (16 + jj) * 66 + b_pw] + gg[j];
            float xo = gt[(24 + jj) * 66 + b_pw] + gt[GT_GRP + (24 + jj) * 66 + b_pw] + go[j];
            float f = sigmoidf_(xf), ig = sigmoidf_(xi);
            float g = tanhf(xg),     o  = sigmoidf_(xo);
            cv[j] = f * co[j] + ig * g;
            hv[j] = o * tanhf(cv[j]);
        }
        *(float2*)&cs[b_pw * 8 + jj0] = make_float2(cv[0], cv[1]);
        hTw[(jb * 8 + jj0 + 0) * 64 + b_pw] = hv[0];
        hTw[(jb * 8 + jj0 + 1) * 64 + b_pw] = hv[1];
        *(float2*)&layer_out[((size_t)b_pw * T_ + t) * H_ + jb * 8 + jj0] =
            make_float2(hv[0], hv[1]);
        if (t == T_ - 1) {
            size_t hb2 = (size_t)B_ * T_ * H_ + (size_t)l * B_ * H_ +
                         (size_t)b_pw * H_ + jb * 8 + jj0;
            *(float2*)&outp[hb2] = make_float2(hv[0], hv[1]);
            *(float2*)&outp[hb2 + (size_t)L_ * B_ * H_] = make_float2(cv[0], cv[1]);
        }
    }
}

extern "C" void kernel_launch(void* const* d_in, const int* in_sizes, int n_in,
                              void* d_out, int out_size)
{
    const float* x  = (const float*)d_in[0];
    const float* W  = (const float*)d_in[1];
    const float* bs = (const float*)d_in[2];
    const float* h0 = (const float*)d_in[3];
    const float* c0 = (const float*)d_in[4];
    float* out = (float*)d_out;

    float *gin, *mid, *hT;
    cudaGetSymbolAddress((void**)&gin, g_gin);
    cudaGetSymbolAddress((void**)&mid, g_mid);
    cudaGetSymbolAddress((void**)&hT, g_hT);
    float* hT0 = hT;
    float* hT1 = hT + H_ * B_;

    cudaFuncSetAttribute(lstm_seq, cudaFuncAttributeMaxDynamicSharedMemorySize,
                         SMEM_BYTES);

    for (int l = 0; l < L_; l++) {
        const float* layer_in  = (l == 0) ? x   : mid;
        float*       layer_out = (l == 0) ? mid : out;
        const float* Wl = W  + (size_t)l * G_ * K2_;
        const float* bl = bs + (size_t)l * G_;

        h0_transpose<<<256, 256>>>(h0 + (size_t)l * B_ * H_, hT0);
        lstm_in_gemm<<<dim3(64, 256), 256>>>(layer_in, Wl, bl, gin);
        lstm_seq<<<NBLK, 256, SMEM_BYTES>>>(Wl, gin, c0 + (size_t)l * B_ * H_,
                                            hT0, hT1, layer_out, out, l);
    }
}

// round 6
// speedup vs baseline: 1.0379x; 1.0022x over previous
#include <cuda_runtime.h>
#include <math.h>

typedef unsigned long long ull;

#define B_   64
#define T_   512
#define H_   1024
#define L_   2
#define G_   4096
#define K2_  2048
#define NBLK 128

// smem plan (floats): Ws 32768 | hsA 4096 | hsB 4096 | gt 2*32*66=4224 | cs 512
#define WS_OFF   0
#define HSA_OFF  32768
#define HSB_OFF  36864
#define GT_OFF   40960
#define GT_GRP   2112            // 32*66
#define CS_OFF   45184
#define SMEM_FLOATS 45696
#define SMEM_BYTES  (SMEM_FLOATS * 4)

__device__ float g_gin[(size_t)B_ * T_ * G_];
__device__ float g_mid[(size_t)B_ * T_ * H_];
__device__ float g_hT[2][H_ * B_];
__device__ unsigned g_cnt = 0;
__device__ unsigned g_gen = 0;

__device__ __forceinline__ void ffma2(ull& d, ull a, ull b) {
    asm volatile("fma.rn.f32x2 %0, %1, %2, %0;" : "+l"(d) : "l"(a), "l"(b));
}
__device__ __forceinline__ ull dup2(float x) {
    ull r; asm("mov.b64 %0, {%1, %1};" : "=l"(r) : "f"(x)); return r;
}
__device__ __forceinline__ float2 unpack2(ull v) {
    float2 f; asm("mov.b64 {%0, %1}, %2;" : "=f"(f.x), "=f"(f.y) : "l"(v)); return f;
}
__device__ __forceinline__ float sigmoidf_(float x) {
    return __fdividef(1.0f, 1.0f + expf(-x));
}
__device__ __forceinline__ void cp_async16(const float* smem_dst, const float* gsrc) {
    unsigned sa = (unsigned)__cvta_generic_to_shared((void*)smem_dst);
    asm volatile("cp.async.cg.shared.global [%0], [%1], 16;" :: "r"(sa), "l"(gsrc));
}

__device__ __forceinline__ void grid_barrier() {
    __syncthreads();
    if (threadIdx.x == 0) {
        asm volatile("fence.acq_rel.gpu;" ::: "memory");
        unsigned old;
        asm volatile("ld.relaxed.gpu.u32 %0, [%1];" : "=r"(old) : "l"(&g_gen));
        if (atomicAdd(&g_cnt, 1u) == NBLK - 1) {
            asm volatile("st.relaxed.gpu.u32 [%0], %1;" :: "l"(&g_cnt), "r"(0u));
            asm volatile("st.release.gpu.u32 [%0], %1;" :: "l"(&g_gen), "r"(old + 1u));
        } else {
            unsigned cur;
            do {
                asm volatile("ld.acquire.gpu.u32 %0, [%1];" : "=r"(cur) : "l"(&g_gen));
            } while (cur == old);
        }
    }
    __syncthreads();
}

// ---------------------------------------------------------------------------
// h0 transpose: hT[k*64 + b] = h0l[b*H + k]
// ---------------------------------------------------------------------------
__global__ void h0_transpose(const float* __restrict__ h0l, float* __restrict__ hT) {
    int idx = blockIdx.x * 256 + threadIdx.x;
    int b = idx & 63, k = idx >> 6;
    hT[idx] = h0l[b * H_ + k];
}

// ---------------------------------------------------------------------------
// Input GEMM: gin[m, n] = A[m, 0:H] . W[n, 0:H] + bias[n]
// 128(M) x 64(N) tile, BK=16, 256 threads, thread tile 8m x 4n (f32x2 packed)
// (unchanged from R3 — near its FFMA2 floor by model; revisit with tcgen05)
// ---------------------------------------------------------------------------
__global__ void __launch_bounds__(256) lstm_in_gemm(
    const float* __restrict__ A, const float* __restrict__ Wl,
    const float* __restrict__ bl, float* __restrict__ C)
{
    __shared__ float  As[16][128];
    __shared__ float2 Bs[16][2][16][2];

    const int tid = threadIdx.x;
    const int n0 = blockIdx.x * 64;
    const int m0 = blockIdx.y * 128;

    const int ar = tid >> 1, ac = (tid & 1) * 8;
    const float* aptr = A + (size_t)(m0 + ar) * H_ + ac;
    const int wr = tid & 63, wc = (tid >> 6) * 4;
    const float* wptr = Wl + (size_t)(n0 + wr) * K2_ + wc;
    const int btx = wr >> 2, bh = (wr >> 1) & 1, be = wr & 1;

    const int tx = tid & 15, ty = tid >> 4;

    ull acc[4][4];
#pragma unroll
    for (int i = 0; i < 4; i++)
#pragma unroll
        for (int j = 0; j < 4; j++) acc[i][j] = 0ULL;

    float4 a0 = *(const float4*)aptr;
    float4 a1 = *(const float4*)(aptr + 4);
    float4 w0 = *(const float4*)wptr;

    for (int k0 = 0; k0 < H_; k0 += 16) {
        As[ac + 0][ar] = a0.x; As[ac + 1][ar] = a0.y;
        As[ac + 2][ar] = a0.z; As[ac + 3][ar] = a0.w;
        As[ac + 4][ar] = a1.x; As[ac + 5][ar] = a1.y;
        As[ac + 6][ar] = a1.z; As[ac + 7][ar] = a1.w;
        Bs[wc + 0][bh][btx][be] = make_float2(w0.x, w0.x);
        Bs[wc + 1][bh][btx][be] = make_float2(w0.y, w0.y);
        Bs[wc + 2][bh][btx][be] = make_float2(w0.z, w0.z);
        Bs[wc + 3][bh][btx][be] = make_float2(w0.w, w0.w);
        __syncthreads();

        if (k0 + 16 < H_) {
            a0 = *(const float4*)(aptr + k0 + 16);
            a1 = *(const float4*)(aptr + k0 + 20);
            w0 = *(const float4*)(wptr + k0 + 16);
        }

#pragma unroll
        for (int kk = 0; kk < 16; kk++) {
            ulonglong2 aL = *(const ulonglong2*)&As[kk][ty * 8];
            ulonglong2 aH = *(const ulonglong2*)&As[kk][ty * 8 + 4];
            ulonglong2 b0 = *(const ulonglong2*)&Bs[kk][0][tx][0];
            ulonglong2 b1 = *(const ulonglong2*)&Bs[kk][1][tx][0];
            ffma2(acc[0][0], aL.x, b0.x); ffma2(acc[0][1], aL.x, b0.y);
            ffma2(acc[0][2], aL.x, b1.x); ffma2(acc[0][3], aL.x, b1.y);
            ffma2(acc[1][0], aL.y, b0.x); ffma2(acc[1][1], aL.y, b0.y);
            ffma2(acc[1][2], aL.y, b1.x); ffma2(acc[1][3], aL.y, b1.y);
            ffma2(acc[2][0], aH.x, b0.x); ffma2(acc[2][1], aH.x, b0.y);
            ffma2(acc[2][2], aH.x, b1.x); ffma2(acc[2][3], aH.x, b1.y);
            ffma2(acc[3][0], aH.y, b0.x); ffma2(acc[3][1], aH.y, b0.y);
            ffma2(acc[3][2], aH.y, b1.x); ffma2(acc[3][3], aH.y, b1.y);
        }
        __syncthreads();
    }

    float4 bias = *(const float4*)&bl[n0 + tx * 4];
#pragma unroll
    for (int mi = 0; mi < 4; mi++) {
        float2 c0 = unpack2(acc[mi][0]);
        float2 c1 = unpack2(acc[mi][1]);
        float2 c2 = unpack2(acc[mi][2]);
        float2 c3 = unpack2(acc[mi][3]);
        size_t r = (size_t)(m0 + ty * 8 + 2 * mi) * G_ + n0 + tx * 4;
        *(float4*)&C[r] = make_float4(c0.x + bias.x, c1.x + bias.y,
                                      c2.x + bias.z, c3.x + bias.w);
        *(float4*)&C[r + G_] = make_float4(c0.y + bias.x, c1.y + bias.y,
                                           c2.y + bias.z, c3.y + bias.w);
    }
}

// ---------------------------------------------------------------------------
// Persistent recurrent kernel, 256 threads, k-split across 2 warp-groups.
// Block jb owns gate cols {g*H + jb*8 + jj : g<4, jj<8}; W slice in smem.
// Group 0: k in [0,512) (local kk2 0..15 of each 64-k tile); group 1: rest.
// ---------------------------------------------------------------------------
__global__ void __launch_bounds__(256, 1) lstm_seq(
    const float* __restrict__ Wl, const float* __restrict__ gin,
    const float* __restrict__ c0l, float* __restrict__ hT0,
    float* __restrict__ hT1, float* __restrict__ layer_out,
    float* __restrict__ outp, int l)
{
    extern __shared__ float sm[];
    float* Ws  = sm + WS_OFF;
    float* hsA = sm + HSA_OFF;
    float* hsB = sm + HSB_OFF;
    float* gt  = sm + GT_OFF;    // [grp][col stride 66][64 b]
    float* cs  = sm + CS_OFF;    // [b*8 + jj]

    const int tid = threadIdx.x;
    const int jb  = blockIdx.x;
    const int lane = tid & 31, warp = tid >> 5;
    const int grp  = warp >> 2;          // k-split group
    const int w4   = warp & 3;
    const int col2 = lane & 15;          // col pair: cols (2c, 2c+1)
    const int msel = lane >> 4;
    const int m_base = w4 * 16 + msel * 8;

    // --- Ws fill (once per layer): Ws4[k2*16+cf] = {w(2k2,c0), w(2k2,c1), w(2k2+1,c0), w(2k2+1,c1)}
    {
        const int cf = tid & 15;
        const int c0 = 2 * cf, c1 = c0 + 1;
        const int gr0 = (c0 >> 3) * H_ + jb * 8 + (c0 & 7);
        const int gr1 = (c1 >> 3) * H_ + jb * 8 + (c1 & 7);
        const float* r0 = Wl + (size_t)gr0 * K2_ + H_;
        const float* r1 = Wl + (size_t)gr1 * K2_ + H_;
        const int k2s = (tid >> 4) * 32;
        for (int q = 0; q < 32; q++) {
            int k2 = k2s + q;
            float2 va = *(const float2*)(r0 + 2 * k2);
            float2 vb = *(const float2*)(r1 + 2 * k2);
            ((float4*)Ws)[k2 * 16 + cf] = make_float4(va.x, vb.x, va.y, vb.y);
        }
    }
    for (int i = tid; i < 512; i += 256)
        cs[i] = c0l[(i >> 3) * H_ + jb * 8 + (i & 7)];
    __syncthreads();

    const int b_pw = tid & 63;
    const int jj0  = (tid >> 6) * 2;     // 0,2,4,6

    for (int t = 0; t < T_; t++) {
        const float* hTr = (t & 1) ? hT1 : hT0;
        float*       hTw = (t & 1) ? hT0 : hT1;

        // gin prefetch (independent of h) — issue before the barrier
        const float* gp = gin + ((size_t)b_pw * T_ + t) * G_ + jb * 8 + jj0;
        float2 pf = __ldg((const float2*)gp);
        float2 pi = __ldg((const float2*)(gp + H_));
        float2 pg = __ldg((const float2*)(gp + 2 * H_));
        float2 po = __ldg((const float2*)(gp + 3 * H_));

        grid_barrier();

        // stage tile 0 (64 k x 64 b = 16KB)
#pragma unroll
        for (int w = 0; w < 4; w++)
            cp_async16(hsA + (tid + w * 256) * 4, hTr + (tid + w * 256) * 4);
        asm volatile("cp.async.commit_group;");

        ull acc[8];
#pragma unroll
        for (int i = 0; i < 8; i++) acc[i] = 0ULL;

        for (int kt = 0; kt < 16; kt++) {
            float* hcur = (kt & 1) ? hsB : hsA;
            float* hnxt = (kt & 1) ? hsA : hsB;
            if (kt < 15) {
                const float* src = hTr + (kt + 1) * 4096;
#pragma unroll
                for (int w = 0; w < 4; w++)
                    cp_async16(hnxt + (tid + w * 256) * 4, src + (tid + w * 256) * 4);
                asm volatile("cp.async.commit_group;");
                asm volatile("cp.async.wait_group 1;");
            } else {
                asm volatile("cp.async.wait_group 0;");
            }
            __syncthreads();

            const float4* Wv = (const float4*)Ws + (size_t)(kt * 32 + grp * 16) * 16;
            const float*  hb = hcur + grp * 32 * 64;
#pragma unroll
            for (int kk = 0; kk < 16; kk++) {
                float4 w = Wv[kk * 16 + col2];
                ull w00 = dup2(w.x), w01 = dup2(w.y);
                ull w10 = dup2(w.z), w11 = dup2(w.w);
                const float* hr = hb + (2 * kk) * 64 + m_base;
                ulonglong2 aL0 = *(const ulonglong2*)hr;
                ulonglong2 aH0 = *(const ulonglong2*)(hr + 4);
                ulonglong2 aL1 = *(const ulonglong2*)(hr + 64);
                ulonglong2 aH1 = *(const ulonglong2*)(hr + 68);
                ffma2(acc[0], aL0.x, w00); ffma2(acc[1], aL0.x, w01);
                ffma2(acc[2], aL0.y, w00); ffma2(acc[3], aL0.y, w01);
                ffma2(acc[4], aH0.x, w00); ffma2(acc[5], aH0.x, w01);
                ffma2(acc[6], aH0.y, w00); ffma2(acc[7], aH0.y, w01);
                ffma2(acc[0], aL1.x, w10); ffma2(acc[1], aL1.x, w11);
                ffma2(acc[2], aL1.y, w10); ffma2(acc[3], aL1.y, w11);
                ffma2(acc[4], aH1.x, w10); ffma2(acc[5], aH1.x, w11);
                ffma2(acc[6], aH1.y, w10); ffma2(acc[7], aH1.y, w11);
            }
            __syncthreads();
        }

        // partial gates -> smem (per group slab; stride 66 kills bank conflicts)
        float* gslab = gt + grp * GT_GRP;
#pragma unroll
        for (int mi = 0; mi < 4; mi++) {
            float2 v0 = unpack2(acc[mi * 2 + 0]);   // col 2*col2, rows m_base+2mi..+1
            float2 v1 = unpack2(acc[mi * 2 + 1]);   // col 2*col2+1
            *(float2*)&gslab[(2 * col2 + 0) * 66 + m_base + 2 * mi] = v0;
            *(float2*)&gslab[(2 * col2 + 1) * 66 + m_base + 2 * mi] = v1;
        }
        __syncthreads();

        // pointwise: thread owns batch b_pw, cols jj0, jj0+1
        float2 c_old = *(float2*)&cs[b_pw * 8 + jj0];
        float co[2] = {c_old.x, c_old.y};
        float gf[2] = {pf.x, pf.y}, gi2[2] = {pi.x, pi.y};
        float gg[2] = {pg.x, pg.y}, go[2] = {po.x, po.y};
        float hv[2], cv[2];
#pragma unroll
        for (int j = 0; j < 2; j++) {
            const int jj = jj0 + j;
            float xf = gt[jj * 66 + b_pw]        + gt[GT_GRP + jj * 66 + b_pw]        + gf[j];
            float xi = gt[(8 + jj) * 66 + b_pw]  + gt[GT_GRP + (8 + jj) * 66 + b_pw]  + gi2[j];
            float xg = gt[(16 + jj) * 66 + b_pw] + gt[GT_GRP + (16 + jj) * 66 + b_pw] + gg[j];
            float xo = gt[(24 + jj) * 66 + b_pw] + gt[GT_GRP + (24 + jj) * 66 + b_pw] + go[j];
            float f = sigmoidf_(xf), ig = sigmoidf_(xi);
            float g = tanhf(xg),     o  = sigmoidf_(xo);
            cv[j] = f * co[j] + ig * g;
            hv[j] = o * tanhf(cv[j]);
        }
        *(float2*)&cs[b_pw * 8 + jj0] = make_float2(cv[0], cv[1]);
        hTw[(jb * 8 + jj0 + 0) * 64 + b_pw] = hv[0];
        hTw[(jb * 8 + jj0 + 1) * 64 + b_pw] = hv[1];
        *(float2*)&layer_out[((size_t)b_pw * T_ + t) * H_ + jb * 8 + jj0] =
            make_float2(hv[0], hv[1]);
        if (t == T_ - 1) {
            size_t hb2 = (size_t)B_ * T_ * H_ + (size_t)l * B_ * H_ +
                         (size_t)b_pw * H_ + jb * 8 + jj0;
            *(float2*)&outp[hb2] = make_float2(hv[0], hv[1]);
            *(float2*)&outp[hb2 + (size_t)L_ * B_ * H_] = make_float2(cv[0], cv[1]);
        }
    }
}

extern "C" void kernel_launch(void* const* d_in, const int* in_sizes, int n_in,
                              void* d_out, int out_size)
{
    const float* x  = (const float*)d_in[0];
    const float* W  = (const float*)d_in[1];
    const float* bs = (const float*)d_in[2];
    const float* h0 = (const float*)d_in[3];
    const float* c0 = (const float*)d_in[4];
    float* out = (float*)d_out;

    float *gin, *mid, *hT;
    cudaGetSymbolAddress((void**)&gin, g_gin);
    cudaGetSymbolAddress((void**)&mid, g_mid);
    cudaGetSymbolAddress((void**)&hT, g_hT);
    float* hT0 = hT;
    float* hT1 = hT + H_ * B_;

    cudaFuncSetAttribute(lstm_seq, cudaFuncAttributeMaxDynamicSharedMemorySize,
                         SMEM_BYTES);

    for (int l = 0; l < L_; l++) {
        const float* layer_in  = (l == 0) ? x   : mid;
        float*       layer_out = (l == 0) ? mid : out;
        const float* Wl = W  + (size_t)l * G_ * K2_;
        const float* bl = bs + (size_t)l * G_;

        h0_transpose<<<256, 256>>>(h0 + (size_t)l * B_ * H_, hT0);
        lstm_in_gemm<<<dim3(64, 256), 256>>>(layer_in, Wl, bl, gin);
        lstm_seq<<<NBLK, 256, SMEM_BYTES>>>(Wl, gin, c0 + (size_t)l * B_ * H_,
                                            hT0, hT1, layer_out, out, l);
    }
}

// round 7
// speedup vs baseline: 1.4252x; 1.3731x over previous
#include <cuda_runtime.h>
#include <math.h>
typedef unsigned int uint;

#define B_   64
#define T_   512
#define H_   1024
#define L_   2
#define G_   4096
#define K2_  2048
#define NBLK 128

#define WF_OFF   0
#define HS_OFF   32768
#define GT_OFF   41984
#define GT_GRP   2112
#define CS_OFF   46208
#define SM_FLOATS 46720
#define SM_BYTES  (SM_FLOATS * 4)
#define GEMM_SM_BYTES 49152

__device__ float g_gin[(size_t)B_ * T_ * G_];
__device__ float g_mid[(size_t)B_ * T_ * H_];
__device__ float g_hT[2][H_ * B_];
__device__ unsigned g_cnt = 0;
__device__ unsigned g_gen = 0;

__device__ __forceinline__ uint f_hi(float x) { return __float_as_uint(x) & 0xFFFFE000u; }
__device__ __forceinline__ uint f_lo(float x, uint h) { return __float_as_uint(x - __uint_as_float(h)); }
__device__ __forceinline__ void mma_tf32(float4& c, const uint4& a, uint b0, uint b1) {
    asm volatile(
        "mma.sync.aligned.m16n8k8.row.col.f32.tf32.tf32.f32 "
        "{%0,%1,%2,%3}, {%4,%5,%6,%7}, {%8,%9}, {%0,%1,%2,%3};"
        : "+f"(c.x), "+f"(c.y), "+f"(c.z), "+f"(c.w)
        : "r"(a.x), "r"(a.y), "r"(a.z), "r"(a.w), "r"(b0), "r"(b1));
}
__device__ __forceinline__ float sigmoidf_(float x) { return __fdividef(1.0f, 1.0f + expf(-x)); }
__device__ __forceinline__ void cp_async16(const float* smem_dst, const float* gsrc) {
    unsigned sa = (unsigned)__cvta_generic_to_shared((void*)smem_dst);
    asm volatile("cp.async.cg.shared.global [%0], [%1], 16;" :: "r"(sa), "l"(gsrc));
}
__device__ __forceinline__ void grid_barrier() {
    __syncthreads();
    if (threadIdx.x == 0) {
        asm volatile("fence.acq_rel.gpu;" ::: "memory");
        unsigned old;
        asm volatile("ld.relaxed.gpu.u32 %0, [%1];" : "=r"(old) : "l"(&g_gen));
        if (atomicAdd(&g_cnt, 1u) == NBLK - 1) {
            asm volatile("st.relaxed.gpu.u32 [%0], %1;" :: "l"(&g_cnt), "r"(0u));
            asm volatile("st.release.gpu.u32 [%0], %1;" :: "l"(&g_gen), "r"(old + 1u));
        } else {
            unsigned cur;
            do { asm volatile("ld.acquire.gpu.u32 %0, [%1];" : "=r"(cur) : "l"(&g_gen)); }
            while (cur == old);
        }
    }
    __syncthreads();
}

// ---------------------------------------------------------------------------
// Input GEMM (3xTF32 mma): gin[m,n] = A[m,0:H].W[n,0:H] + bias[n]
// Block 128Mx64N, BK=16, 256 thr, warp tile 32x32, smem fragments pre-split.
// ---------------------------------------------------------------------------
__global__ void __launch_bounds__(256, 2) lstm_in_gemm(
    const float* __restrict__ A, const float* __restrict__ Wl,
    const float* __restrict__ bl, float* __restrict__ C)
{
    extern __shared__ uint4 smg[];
    uint4* Af = smg;          // [buf2][chunk2][mtile8][hl2][lane32]
    uint4* Bf = smg + 2048;   // [buf2][chunk2][ntile8][lane32]

    const int tid = threadIdx.x, n0 = blockIdx.x * 64, m0 = blockIdx.y * 128;
    const int lane = tid & 31, warp = tid >> 5;
    const int wm = warp >> 1, wn = warp & 1;
    const int g = lane >> 2, tg = lane & 3;

    const size_t rA0 = (size_t)(m0 + warp * 16 + g) * H_;
    const size_t rA1 = rA0 + (size_t)8 * H_;
    const size_t rB0 = (size_t)(n0 + warp * 8 + g) * K2_;

    float a_[8], b_[4];
    float4 cc[2][4];
#pragma unroll
    for (int i = 0; i < 2; i++)
#pragma unroll
        for (int j = 0; j < 4; j++) cc[i][j] = make_float4(0.f, 0.f, 0.f, 0.f);

#define LOADG(k0_) do {                                                   \
    a_[0] = A[rA0 + (k0_) + tg];     a_[1] = A[rA1 + (k0_) + tg];         \
    a_[2] = A[rA0 + (k0_) + tg + 4]; a_[3] = A[rA1 + (k0_) + tg + 4];     \
    a_[4] = A[rA0 + (k0_) + 8 + tg];     a_[5] = A[rA1 + (k0_) + 8 + tg]; \
    a_[6] = A[rA0 + (k0_) + 8 + tg + 4]; a_[7] = A[rA1 + (k0_) + 8 + tg + 4]; \
    b_[0] = Wl[rB0 + (k0_) + tg];     b_[1] = Wl[rB0 + (k0_) + tg + 4];   \
    b_[2] = Wl[rB0 + (k0_) + 8 + tg]; b_[3] = Wl[rB0 + (k0_) + 8 + tg + 4]; \
} while (0)

#define STAGE(buf_) do {                                                  \
    _Pragma("unroll")                                                     \
    for (int ch = 0; ch < 2; ch++) {                                      \
        uint4 hi, lo;                                                     \
        hi.x = f_hi(a_[ch*4+0]); lo.x = f_lo(a_[ch*4+0], hi.x);           \
        hi.y = f_hi(a_[ch*4+1]); lo.y = f_lo(a_[ch*4+1], hi.y);           \
        hi.z = f_hi(a_[ch*4+2]); lo.z = f_lo(a_[ch*4+2], hi.z);           \
        hi.w = f_hi(a_[ch*4+3]); lo.w = f_lo(a_[ch*4+3], hi.w);           \
        Af[(((buf_)*2 + ch)*8 + warp)*64 + lane]      = hi;               \
        Af[(((buf_)*2 + ch)*8 + warp)*64 + 32 + lane] = lo;               \
        uint4 bb;                                                         \
        bb.x = f_hi(b_[ch*2+0]); bb.z = f_lo(b_[ch*2+0], bb.x);           \
        bb.y = f_hi(b_[ch*2+1]); bb.w = f_lo(b_[ch*2+1], bb.y);           \
        Bf[(((buf_)*2 + ch)*8 + warp)*32 + lane] = bb;                    \
    }                                                                     \
} while (0)

    LOADG(0);
    STAGE(0);
    __syncthreads();

    for (int it = 0; it < 64; it++) {
        const int buf = it & 1;
        if (it < 63) LOADG((it + 1) * 16);
#pragma unroll
        for (int ch = 0; ch < 2; ch++) {
            const int base = (buf * 2 + ch) * 8;
            uint4 ah0 = Af[(base + wm * 2 + 0) * 64 + lane];
            uint4 al0 = Af[(base + wm * 2 + 0) * 64 + 32 + lane];
            uint4 ah1 = Af[(base + wm * 2 + 1) * 64 + lane];
            uint4 al1 = Af[(base + wm * 2 + 1) * 64 + 32 + lane];
            uint4 bv0 = Bf[(base + wn * 4 + 0) * 32 + lane];
            uint4 bv1 = Bf[(base + wn * 4 + 1) * 32 + lane];
            uint4 bv2 = Bf[(base + wn * 4 + 2) * 32 + lane];
            uint4 bv3 = Bf[(base + wn * 4 + 3) * 32 + lane];
            mma_tf32(cc[0][0], ah0, bv0.x, bv0.y); mma_tf32(cc[0][1], ah0, bv1.x, bv1.y);
            mma_tf32(cc[0][2], ah0, bv2.x, bv2.y); mma_tf32(cc[0][3], ah0, bv3.x, bv3.y);
            mma_tf32(cc[1][0], ah1, bv0.x, bv0.y); mma_tf32(cc[1][1], ah1, bv1.x, bv1.y);
            mma_tf32(cc[1][2], ah1, bv2.x, bv2.y); mma_tf32(cc[1][3], ah1, bv3.x, bv3.y);
            mma_tf32(cc[0][0], ah0, bv0.z, bv0.w); mma_tf32(cc[0][1], ah0, bv1.z, bv1.w);
            mma_tf32(cc[0][2], ah0, bv2.z, bv2.w); mma_tf32(cc[0][3], ah0, bv3.z, bv3.w);
            mma_tf32(cc[1][0], ah1, bv0.z, bv0.w); mma_tf32(cc[1][1], ah1, bv1.z, bv1.w);
            mma_tf32(cc[1][2], ah1, bv2.z, bv2.w); mma_tf32(cc[1][3], ah1, bv3.z, bv3.w);
            mma_tf32(cc[0][0], al0, bv0.x, bv0.y); mma_tf32(cc[0][1], al0, bv1.x, bv1.y);
            mma_tf32(cc[0][2], al0, bv2.x, bv2.y); mma_tf32(cc[0][3], al0, bv3.x, bv3.y);
            mma_tf32(cc[1][0], al1, bv0.x, bv0.y); mma_tf32(cc[1][1], al1, bv1.x, bv1.y);
            mma_tf32(cc[1][2], al1, bv2.x, bv2.y); mma_tf32(cc[1][3], al1, bv3.x, bv3.y);
        }
        if (it < 63) STAGE((it + 1) & 1);
        __syncthreads();
    }
#undef LOADG
#undef STAGE

#pragma unroll
    for (int mt = 0; mt < 2; mt++)
#pragma unroll
        for (int nt = 0; nt < 4; nt++) {
            const int row = m0 + wm * 32 + mt * 16 + g;
            const int col = n0 + wn * 32 + nt * 8 + 2 * tg;
            const float2 bias = *(const float2*)&bl[col];
            float4 v = cc[mt][nt];
            *(float2*)&C[(size_t)row * G_ + col] = make_float2(v.x + bias.x, v.y + bias.y);
            *(float2*)&C[(size_t)(row + 8) * G_ + col] = make_float2(v.z + bias.x, v.w + bias.y);
        }
}

// ---------------------------------------------------------------------------
// Persistent recurrence (3xTF32 mma), 256 thr, 128 blocks, grid barrier.
// Block jb: M=32 gate cols, N=64 batch, K=1024. W fragments in smem fp32.
// ---------------------------------------------------------------------------
__global__ void __launch_bounds__(256, 1) lstm_seq(
    const float* __restrict__ Wl, const float* __restrict__ gin,
    const float* __restrict__ c0l, const float* __restrict__ h0l,
    float* __restrict__ hT0, float* __restrict__ hT1,
    float* __restrict__ layer_out, float* __restrict__ outp, int l)
{
    extern __shared__ float sm[];
    float* hsA = sm + HS_OFF;
    float* hsB = sm + HS_OFF + 4608;
    float* gt  = sm + GT_OFF;
    float* cs  = sm + CS_OFF;

    const int tid = threadIdx.x, jb = blockIdx.x;
    const int lane = tid & 31, warp = tid >> 5;
    const int wn = warp & 3, kw = warp >> 2;
    const int g = lane >> 2, tig = lane & 3;

    // W fragment staging (once per layer): Wf[mt][k8][lane][reg] fp32
    {
        const int c = tid >> 3;
        const int kbase = (tid & 7) * 128;
        const int gr = (c >> 3) * H_ + jb * 8 + (c & 7);
        const float* wp = Wl + (size_t)gr * K2_ + H_ + kbase;
        const int mt = c >> 4, rin = c & 15;
        const int gg = rin & 7, row8 = rin >> 3;
        for (int q = 0; q < 32; q++) {
            float4 v = *(const float4*)(wp + q * 4);
            const int k = kbase + q * 4;
            const int k8 = k >> 3;
            const int regb = row8 + 2 * ((k >> 2) & 1);
            float* d = sm + WF_OFF + (size_t)(mt * 128 + k8) * 128 + regb;
            d[(gg * 4 + 0) * 4] = v.x; d[(gg * 4 + 1) * 4] = v.y;
            d[(gg * 4 + 2) * 4] = v.z; d[(gg * 4 + 3) * 4] = v.w;
        }
    }
    for (int i = tid; i < 512; i += 256)
        cs[i] = c0l[(i >> 3) * H_ + jb * 8 + (i & 7)];
    for (int q = 0; q < 2; q++) {              // h0 -> hT0 (this block's k slice)
        const int idx = tid + q * 256;
        const int k = jb * 8 + (idx >> 6), b = idx & 63;
        hT0[k * 64 + b] = h0l[b * H_ + k];
    }

    const uint4* Wfp = (const uint4*)(sm + WF_OFF);
    const int b_pw = tid & 63;
    const int jj0  = (tid >> 6) * 2;

    for (int t = 0; t < T_; t++) {
        const float* hTr = (t & 1) ? hT1 : hT0;
        float*       hTw = (t & 1) ? hT0 : hT1;

        const float* gp = gin + ((size_t)b_pw * T_ + t) * G_ + jb * 8 + jj0;
        float2 pf = __ldg((const float2*)gp);
        float2 pi = __ldg((const float2*)(gp + H_));
        float2 pg = __ldg((const float2*)(gp + 2 * H_));
        float2 po = __ldg((const float2*)(gp + 3 * H_));

        grid_barrier();

#pragma unroll
        for (int w = 0; w < 4; w++) {
            const int idx = tid + w * 256;
            cp_async16(hsA + (idx >> 4) * 72 + (idx & 15) * 4, hTr + idx * 4);
        }
        asm volatile("cp.async.commit_group;");

        float4 aHH[2][2], aHL[2][2], aLH[2][2];
#pragma unroll
        for (int i = 0; i < 2; i++)
#pragma unroll
            for (int j = 0; j < 2; j++) {
                aHH[i][j] = make_float4(0.f, 0.f, 0.f, 0.f);
                aHL[i][j] = make_float4(0.f, 0.f, 0.f, 0.f);
                aLH[i][j] = make_float4(0.f, 0.f, 0.f, 0.f);
            }

        for (int kt = 0; kt < 16; kt++) {
            float* hcur = (kt & 1) ? hsB : hsA;
            float* hnxt = (kt & 1) ? hsA : hsB;
            if (kt < 15) {
                const float* src = hTr + (kt + 1) * 4096;
#pragma unroll
                for (int w = 0; w < 4; w++) {
                    const int idx = tid + w * 256;
                    cp_async16(hnxt + (idx >> 4) * 72 + (idx & 15) * 4, src + idx * 4);
                }
                asm volatile("cp.async.commit_group;");
                asm volatile("cp.async.wait_group 1;");
            } else {
                asm volatile("cp.async.wait_group 0;");
            }
            __syncthreads();

#pragma unroll
            for (int r = 0; r < 4; r++) {
                const int k8g = kt * 8 + 2 * r + kw;
                uint4 ah[2], al[2];
#pragma unroll
                for (int mt = 0; mt < 2; mt++) {
                    uint4 w = Wfp[(size_t)(mt * 128 + k8g) * 32 + lane];
                    ah[mt].x = w.x & 0xFFFFE000u; al[mt].x = f_lo(__uint_as_float(w.x), ah[mt].x);
                    ah[mt].y = w.y & 0xFFFFE000u; al[mt].y = f_lo(__uint_as_float(w.y), ah[mt].y);
                    ah[mt].z = w.z & 0xFFFFE000u; al[mt].z = f_lo(__uint_as_float(w.z), ah[mt].z);
                    ah[mt].w = w.w & 0xFFFFE000u; al[mt].w = f_lo(__uint_as_float(w.w), ah[mt].w);
                }
                uint b0h[2], b0l[2], b1h[2], b1l[2];
                const int kr = (2 * r + kw) * 8 + tig;
#pragma unroll
                for (int nt = 0; nt < 2; nt++) {
                    const int bn = (wn * 2 + nt) * 8;
                    float b0 = hcur[kr * 72 + bn + g];
                    float b1 = hcur[(kr + 4) * 72 + bn + g];
                    b0h[nt] = f_hi(b0); b0l[nt] = f_lo(b0, b0h[nt]);
                    b1h[nt] = f_hi(b1); b1l[nt] = f_lo(b1, b1h[nt]);
                }
                mma_tf32(aHH[0][0], ah[0], b0h[0], b1h[0]);
                mma_tf32(aHH[0][1], ah[0], b0h[1], b1h[1]);
                mma_tf32(aHH[1][0], ah[1], b0h[0], b1h[0]);
                mma_tf32(aHH[1][1], ah[1], b0h[1], b1h[1]);
                mma_tf32(aHL[0][0], ah[0], b0l[0], b1l[0]);
                mma_tf32(aHL[0][1], ah[0], b0l[1], b1l[1]);
                mma_tf32(aHL[1][0], ah[1], b0l[0], b1l[0]);
                mma_tf32(aHL[1][1], ah[1], b0l[1], b1l[1]);
                mma_tf32(aLH[0][0], al[0], b0h[0], b1h[0]);
                mma_tf32(aLH[0][1], al[0], b0h[1], b1h[1]);
                mma_tf32(aLH[1][0], al[1], b0h[0], b1h[0]);
                mma_tf32(aLH[1][1], al[1], b0h[1], b1h[1]);
            }
            __syncthreads();
        }

        float* slab = gt + kw * GT_GRP;
#pragma unroll
        for (int mt = 0; mt < 2; mt++)
#pragma unroll
            for (int nt = 0; nt < 2; nt++) {
                float4 c;
                c.x = aHH[mt][nt].x + aHL[mt][nt].x + aLH[mt][nt].x;
                c.y = aHH[mt][nt].y + aHL[mt][nt].y + aLH[mt][nt].y;
                c.z = aHH[mt][nt].z + aHL[mt][nt].z + aLH[mt][nt].z;
                c.w = aHH[mt][nt].w + aHL[mt][nt].w + aLH[mt][nt].w;
                const int bn = (wn * 2 + nt) * 8;
                const int colr = mt * 16 + g;
                *(float2*)&slab[colr * 66 + bn + 2 * tig] = make_float2(c.x, c.y);
                *(float2*)&slab[(colr + 8) * 66 + bn + 2 * tig] = make_float2(c.z, c.w);
            }
        __syncthreads();

        float2 c_old = *(float2*)&cs[b_pw * 8 + jj0];
        float co[2] = {c_old.x, c_old.y};
        float gf[2] = {pf.x, pf.y}, gi2[2] = {pi.x, pi.y};
        float gg2[2] = {pg.x, pg.y}, go[2] = {po.x, po.y};
        float hv[2], cv[2];
#pragma unroll
        for (int j = 0; j < 2; j++) {
            const int jj = jj0 + j;
            float xf = gt[jj * 66 + b_pw]        + gt[GT_GRP + jj * 66 + b_pw]        + gf[j];
            float xi = gt[(8 + jj) * 66 + b_pw]  + gt[GT_GRP + (8 + jj) * 66 + b_pw]  + gi2[j];
            float xg = gt[(16 + jj) * 66 + b_pw] + gt[GT_GRP + (16 + jj) * 66 + b_pw] + gg2[j];
            float xo = gt[(24 + jj) * 66 + b_pw] + gt[GT_GRP + (24 + jj) * 66 + b_pw] + go[j];
            float f = sigmoidf_(xf), ig = sigmoidf_(xi);
            float gv = tanhf(xg),    o  = sigmoidf_(xo);
            cv[j] = f * co[j] + ig * gv;
            hv[j] = o * tanhf(cv[j]);
        }
        *(float2*)&cs[b_pw * 8 + jj0] = make_float2(cv[0], cv[1]);
        hTw[(jb * 8 + jj0 + 0) * 64 + b_pw] = hv[0];
        hTw[(jb * 8 + jj0 + 1) * 64 + b_pw] = hv[1];
        *(float2*)&layer_out[((size_t)b_pw * T_ + t) * H_ + jb * 8 + jj0] =
            make_float2(hv[0], hv[1]);
        if (t == T_ - 1) {
            size_t hb2 = (size_t)B_ * T_ * H_ + (size_t)l * B_ * H_ +
                         (size_t)b_pw * H_ + jb * 8 + jj0;
            *(float2*)&outp[hb2] = make_float2(hv[0], hv[1]);
            *(float2*)&outp[hb2 + (size_t)L_ * B_ * H_] = make_float2(cv[0], cv[1]);
        }
    }
}

extern "C" void kernel_launch(void* const* d_in, const int* in_sizes, int n_in,
                              void* d_out, int out_size)
{
    const float* x  = (const float*)d_in[0];
    const float* W  = (const float*)d_in[1];
    const float* bs = (const float*)d_in[2];
    const float* h0 = (const float*)d_in[3];
    const float* c0 = (const float*)d_in[4];
    float* out = (float*)d_out;

    float *gin, *mid, *hT;
    cudaGetSymbolAddress((void**)&gin, g_gin);
    cudaGetSymbolAddress((void**)&mid, g_mid);
    cudaGetSymbolAddress((void**)&hT, g_hT);
    float* hT0 = hT;
    float* hT1 = hT + H_ * B_;

    cudaFuncSetAttribute(lstm_in_gemm, cudaFuncAttributeMaxDynamicSharedMemorySize,
                         GEMM_SM_BYTES);
    cudaFuncSetAttribute(lstm_seq, cudaFuncAttributeMaxDynamicSharedMemorySize,
                         SM_BYTES);

    for (int l = 0; l < L_; l++) {
        const float* layer_in  = (l == 0) ? x   : mid;
        float*       layer_out = (l == 0) ? mid : out;
        const float* Wl = W  + (size_t)l * G_ * K2_;
        const float* bl = bs + (size_t)l * G_;

        lstm_in_gemm<<<dim3(64, 256), 256, GEMM_SM_BYTES>>>(layer_in, Wl, bl, gin);
        lstm_seq<<<NBLK, 256, SM_BYTES>>>(Wl, gin,
                                          c0 + (size_t)l * B_ * H_,
                                          h0 + (size_t)l * B_ * H_,
                                          hT0, hT1, layer_out, out, l);
    }
}

// round 8
// speedup vs baseline: 1.9368x; 1.3590x over previous
#include <cuda_runtime.h>
#include <math.h>
typedef unsigned int uint;
typedef unsigned short ushort;

#define B_   64
#define T_   512
#define H_   1024
#define L_   2
#define G_   4096
#define K2_  2048
#define NBLK 128

// lstm_seq dynamic smem plan (float units)
#define WH_OFF 0          // W hi fragments: 4096 uint4 = 16384 floats
#define WL_OFF 16384      // W lo fragments: 16384 floats
#define HT_OFF 32768      // h tiles: 2 bufs x (hi 4608 + lo 4608 bf16) = 9216 floats
#define GT_OFF 41984      // gate exchange: 2 x 2112 floats
#define GT_GRP 2112
#define CS_OFF 46208      // cell state: 512 floats
#define SM_FLOATS 46720
#define SM_BYTES  (SM_FLOATS * 4)

__device__ float  g_gin[(size_t)B_ * T_ * G_];
__device__ float  g_mid[(size_t)B_ * T_ * H_];
__device__ ushort g_hbf[2][2][B_ * H_];     // [buf][hi/lo][b*1024+k]
__device__ unsigned g_cnt = 0;
__device__ unsigned g_gen = 0;

__device__ __forceinline__ void mma_bf16(float4& c, const uint4& a, uint b0, uint b1) {
    asm volatile(
        "mma.sync.aligned.m16n8k16.row.col.f32.bf16.bf16.f32 "
        "{%0,%1,%2,%3}, {%4,%5,%6,%7}, {%8,%9}, {%0,%1,%2,%3};"
        : "+f"(c.x), "+f"(c.y), "+f"(c.z), "+f"(c.w)
        : "r"(a.x), "r"(a.y), "r"(a.z), "r"(a.w), "r"(b0), "r"(b1));
}
// split float2 -> (packed bf16 hi pair, packed bf16 lo pair); lane order: low=x
__device__ __forceinline__ uint2 bsplit(float2 v) {
    uint h;
    asm("cvt.rn.bf16x2.f32 %0, %1, %2;" : "=r"(h) : "f"(v.y), "f"(v.x));
    float rx = v.x - __uint_as_float(h << 16);
    float ry = v.y - __uint_as_float(h & 0xFFFF0000u);
    uint l;
    asm("cvt.rn.bf16x2.f32 %0, %1, %2;" : "=r"(l) : "f"(ry), "f"(rx));
    return make_uint2(h, l);
}
__device__ __forceinline__ float sigmoidf_(float x) { return __fdividef(1.0f, 1.0f + expf(-x)); }
__device__ __forceinline__ void cp_async16u(const ushort* smem_dst, const ushort* gsrc) {
    unsigned sa = (unsigned)__cvta_generic_to_shared((void*)smem_dst);
    asm volatile("cp.async.cg.shared.global [%0], [%1], 16;" :: "r"(sa), "l"(gsrc));
}
__device__ __forceinline__ void grid_barrier() {
    __syncthreads();
    if (threadIdx.x == 0) {
        asm volatile("fence.acq_rel.gpu;" ::: "memory");
        unsigned old;
        asm volatile("ld.relaxed.gpu.u32 %0, [%1];" : "=r"(old) : "l"(&g_gen));
        if (atomicAdd(&g_cnt, 1u) == NBLK - 1) {
            asm volatile("st.relaxed.gpu.u32 [%0], %1;" :: "l"(&g_cnt), "r"(0u));
            asm volatile("st.release.gpu.u32 [%0], %1;" :: "l"(&g_gen), "r"(old + 1u));
        } else {
            unsigned cur;
            do { asm volatile("ld.acquire.gpu.u32 %0, [%1];" : "=r"(cur) : "l"(&g_gen)); }
            while (cur == old);
        }
    }
    __syncthreads();
}

// ---------------------------------------------------------------------------
// Input GEMM (3xbf16 m16n8k16): gin[m,n] = A[m,0:H].W[n,0:H] + bias[n]
// Block 128Mx64N, BK=16, 256 thr, warp tile 32x32.
// ---------------------------------------------------------------------------
__global__ void __launch_bounds__(256, 2) lstm_in_gemm(
    const float* __restrict__ A, const float* __restrict__ Wl,
    const float* __restrict__ bl, float* __restrict__ C)
{
    __shared__ uint4 Af[1024];   // [buf2][mt8][hi32|lo32 lanes]
    __shared__ uint4 Bf[512];    // [buf2][nt8][lane32] = (b0h,b1h,b0l,b1l)

    const int tid = threadIdx.x, n0 = blockIdx.x * 64, m0 = blockIdx.y * 128;
    const int lane = tid & 31, warp = tid >> 5;
    const int wm = warp >> 1, wn = warp & 1;
    const int g = lane >> 2, tg = lane & 3;

    const size_t rA0 = (size_t)(m0 + warp * 16 + g) * H_;
    const size_t rA1 = rA0 + (size_t)8 * H_;
    const size_t rB0 = (size_t)(n0 + warp * 8 + g) * K2_;

    float2 a0v, a1v, a2v, a3v, b0v, b1v;
    float4 cc[2][4];
#pragma unroll
    for (int i = 0; i < 2; i++)
#pragma unroll
        for (int j = 0; j < 4; j++) cc[i][j] = make_float4(0.f, 0.f, 0.f, 0.f);

#define LOADG(kb_) do {                                       \
    a0v = *(const float2*)&A[rA0 + (kb_) + tg * 2];           \
    a1v = *(const float2*)&A[rA1 + (kb_) + tg * 2];           \
    a2v = *(const float2*)&A[rA0 + (kb_) + 8 + tg * 2];       \
    a3v = *(const float2*)&A[rA1 + (kb_) + 8 + tg * 2];       \
    b0v = *(const float2*)&Wl[rB0 + (kb_) + tg * 2];          \
    b1v = *(const float2*)&Wl[rB0 + (kb_) + 8 + tg * 2];      \
} while (0)

#define STAGE(buf_) do {                                      \
    uint2 s0 = bsplit(a0v), s1 = bsplit(a1v);                 \
    uint2 s2 = bsplit(a2v), s3 = bsplit(a3v);                 \
    Af[((buf_) * 8 + warp) * 64 + lane]      = make_uint4(s0.x, s1.x, s2.x, s3.x); \
    Af[((buf_) * 8 + warp) * 64 + 32 + lane] = make_uint4(s0.y, s1.y, s2.y, s3.y); \
    uint2 t0 = bsplit(b0v), t1 = bsplit(b1v);                 \
    Bf[((buf_) * 8 + warp) * 32 + lane] = make_uint4(t0.x, t1.x, t0.y, t1.y); \
} while (0)

    LOADG(0);
    STAGE(0);
    __syncthreads();

    for (int it = 0; it < 64; it++) {
        const int buf = it & 1;
        if (it < 63) LOADG((it + 1) * 16);

        const int abase = (buf * 8 + wm * 2) * 64 + lane;
        uint4 aH0 = Af[abase],      aL0 = Af[abase + 32];
        uint4 aH1 = Af[abase + 64], aL1 = Af[abase + 96];
#pragma unroll
        for (int nt = 0; nt < 4; nt++) {
            uint4 bv = Bf[(buf * 8 + wn * 4 + nt) * 32 + lane];
            mma_bf16(cc[0][nt], aH0, bv.x, bv.y);   // HH
            mma_bf16(cc[1][nt], aH1, bv.x, bv.y);
            mma_bf16(cc[0][nt], aH0, bv.z, bv.w);   // HL
            mma_bf16(cc[1][nt], aH1, bv.z, bv.w);
            mma_bf16(cc[0][nt], aL0, bv.x, bv.y);   // LH
            mma_bf16(cc[1][nt], aL1, bv.x, bv.y);
        }
        if (it < 63) STAGE((it + 1) & 1);
        __syncthreads();
    }
#undef LOADG
#undef STAGE

#pragma unroll
    for (int mt = 0; mt < 2; mt++)
#pragma unroll
        for (int nt = 0; nt < 4; nt++) {
            const int row = m0 + wm * 32 + mt * 16 + g;
            const int col = n0 + wn * 32 + nt * 8 + 2 * tg;
            const float2 bias = *(const float2*)&bl[col];
            float4 v = cc[mt][nt];
            *(float2*)&C[(size_t)row * G_ + col] = make_float2(v.x + bias.x, v.y + bias.y);
            *(float2*)&C[(size_t)(row + 8) * G_ + col] = make_float2(v.z + bias.x, v.w + bias.y);
        }
}

// ---------------------------------------------------------------------------
// Persistent recurrence (3xbf16 m16n8k16), 256 thr, 128 blocks, grid barrier.
// Block jb: M=32 gate cols, N=64 batch, K=1024. W pre-split in smem; h
// pre-split at the pointwise and streamed as bf16 hi/lo.
// ---------------------------------------------------------------------------
__global__ void __launch_bounds__(256, 1) lstm_seq(
    const float* __restrict__ Wl, const float* __restrict__ gin,
    const float* __restrict__ c0l, const float* __restrict__ h0l,
    ushort* __restrict__ hHi0, ushort* __restrict__ hLo0,
    ushort* __restrict__ hHi1, ushort* __restrict__ hLo1,
    float* __restrict__ layer_out, float* __restrict__ outp, int l)
{
    extern __shared__ float sm[];
    uint4*  WsH  = (uint4*)(sm + WH_OFF);    // [mt2*64kc][lane32]
    uint4*  WsL  = (uint4*)(sm + WL_OFF);
    ushort* hbuf = (ushort*)(sm + HT_OFF);   // [buf2][hi4608|lo4608], rows stride 72
    float*  gt   = sm + GT_OFF;
    float*  cs   = sm + CS_OFF;

    const int tid = threadIdx.x, jb = blockIdx.x;
    const int lane = tid & 31, warp = tid >> 5;
    const int wn = warp & 3, kw = warp >> 2;

    // --- W fragment staging (once per layer), pre-split bf16
#pragma unroll 1
    for (int q = 0; q < 16; q++) {
        const int fi = q * 256 + tid;               // 0..4095
        const int ln = fi & 31, kc = (fi >> 5) & 63, mt = fi >> 11;
        const int colc = mt * 16 + (ln >> 2);
        const int colc8 = colc + 8;
        const int gr  = (colc  >> 3) * H_ + jb * 8 + (colc  & 7);
        const int gr8 = (colc8 >> 3) * H_ + jb * 8 + (colc8 & 7);
        const int k0 = kc * 16 + (ln & 3) * 2;
        const float* w0 = Wl + (size_t)gr  * K2_ + H_;
        const float* w8 = Wl + (size_t)gr8 * K2_ + H_;
        uint2 s0 = bsplit(*(const float2*)(w0 + k0));
        uint2 s1 = bsplit(*(const float2*)(w8 + k0));
        uint2 s2 = bsplit(*(const float2*)(w0 + k0 + 8));
        uint2 s3 = bsplit(*(const float2*)(w8 + k0 + 8));
        WsH[fi] = make_uint4(s0.x, s1.x, s2.x, s3.x);
        WsL[fi] = make_uint4(s0.y, s1.y, s2.y, s3.y);
    }
    for (int i = tid; i < 512; i += 256)
        cs[i] = c0l[(i >> 3) * H_ + jb * 8 + (i & 7)];
    // h0 -> buf0 bf16 hi/lo (this block's k slice)
#pragma unroll
    for (int q = 0; q < 2; q++) {
        const int idx = tid + q * 256;
        const int k = jb * 8 + (idx >> 6), b = idx & 63;
        float x = h0l[b * H_ + k];
        uint2 s = bsplit(make_float2(x, 0.f));
        hHi0[b * 1024 + k] = (ushort)(s.x & 0xFFFF);
        hLo0[b * 1024 + k] = (ushort)(s.y & 0xFFFF);
    }

    const int b_pw = tid & 63;
    const int jj0  = (tid >> 6) * 2;

    for (int t = 0; t < T_; t++) {
        const ushort* rHi = (t & 1) ? hHi1 : hHi0;
        const ushort* rLo = (t & 1) ? hLo1 : hLo0;
        ushort* wHi = (t & 1) ? hHi0 : hHi1;
        ushort* wLo = (t & 1) ? hLo0 : hLo1;

        const float* gp = gin + ((size_t)b_pw * T_ + t) * G_ + jb * 8 + jj0;
        float2 pf = __ldg((const float2*)gp);
        float2 pi = __ldg((const float2*)(gp + H_));
        float2 pg = __ldg((const float2*)(gp + 2 * H_));
        float2 po = __ldg((const float2*)(gp + 3 * H_));

        grid_barrier();

        // stage chunk 0 (64 k x 64 b, hi+lo)
#pragma unroll
        for (int q = 0; q < 2; q++) {
            const int gix = tid + q * 256;
            const int b = gix >> 3, ko = (gix & 7) * 8;
            ushort* d = hbuf + b * 72 + ko;
            const ushort* s = rHi + b * 1024 + ko;
            cp_async16u(d, s);
            cp_async16u(d + 4608, rLo + b * 1024 + ko);
        }
        asm volatile("cp.async.commit_group;");

        float4 aHH[2][2], aHL[2][2], aLH[2][2];
#pragma unroll
        for (int i = 0; i < 2; i++)
#pragma unroll
            for (int j = 0; j < 2; j++) {
                aHH[i][j] = make_float4(0.f, 0.f, 0.f, 0.f);
                aHL[i][j] = make_float4(0.f, 0.f, 0.f, 0.f);
                aLH[i][j] = make_float4(0.f, 0.f, 0.f, 0.f);
            }

        for (int kt = 0; kt < 16; kt++) {
            const ushort* hc = hbuf + (kt & 1) * 9216;
            if (kt < 15) {
                const int nb = (kt + 1) & 1;
#pragma unroll
                for (int q = 0; q < 2; q++) {
                    const int gix = tid + q * 256;
                    const int b = gix >> 3, ko = (gix & 7) * 8;
                    ushort* d = hbuf + nb * 9216 + b * 72 + ko;
                    cp_async16u(d, rHi + b * 1024 + (kt + 1) * 64 + ko);
                    cp_async16u(d + 4608, rLo + b * 1024 + (kt + 1) * 64 + ko);
                }
                asm volatile("cp.async.commit_group;");
                asm volatile("cp.async.wait_group 1;");
            } else {
                asm volatile("cp.async.wait_group 0;");
            }
            __syncthreads();

#pragma unroll
            for (int r = 0; r < 2; r++) {
                const int kloc = 2 * r + kw;           // k16 within chunk
                const int kg = kt * 4 + kloc;          // global k16 index
                uint4 aH0 = WsH[kg * 32 + lane];
                uint4 aH1 = WsH[(64 + kg) * 32 + lane];
                uint4 aL0 = WsL[kg * 32 + lane];
                uint4 aL1 = WsL[(64 + kg) * 32 + lane];
                uint b0h[2], b1h[2], b0l[2], b1l[2];
#pragma unroll
                for (int nt = 0; nt < 2; nt++) {
                    const int col = (wn * 2 + nt) * 8 + (lane >> 2);
                    const int off = col * 72 + kloc * 16 + (lane & 3) * 2;
                    b0h[nt] = *(const uint*)(hc + off);
                    b1h[nt] = *(const uint*)(hc + off + 8);
                    b0l[nt] = *(const uint*)(hc + 4608 + off);
                    b1l[nt] = *(const uint*)(hc + 4608 + off + 8);
                }
                mma_bf16(aHH[0][0], aH0, b0h[0], b1h[0]);
                mma_bf16(aHH[0][1], aH0, b0h[1], b1h[1]);
                mma_bf16(aHH[1][0], aH1, b0h[0], b1h[0]);
                mma_bf16(aHH[1][1], aH1, b0h[1], b1h[1]);
                mma_bf16(aHL[0][0], aH0, b0l[0], b1l[0]);
                mma_bf16(aHL[0][1], aH0, b0l[1], b1l[1]);
                mma_bf16(aHL[1][0], aH1, b0l[0], b1l[0]);
                mma_bf16(aHL[1][1], aH1, b0l[1], b1l[1]);
                mma_bf16(aLH[0][0], aL0, b0h[0], b1h[0]);
                mma_bf16(aLH[0][1], aL0, b0h[1], b1h[1]);
                mma_bf16(aLH[1][0], aL1, b0h[0], b1h[0]);
                mma_bf16(aLH[1][1], aL1, b0h[1], b1h[1]);
            }
            __syncthreads();
        }

        // gate partials -> slab (kw groups separate)
        float* slab = gt + kw * GT_GRP;
#pragma unroll
        for (int mt = 0; mt < 2; mt++)
#pragma unroll
            for (int nt = 0; nt < 2; nt++) {
                float4 c;
                c.x = aHH[mt][nt].x + aHL[mt][nt].x + aLH[mt][nt].x;
                c.y = aHH[mt][nt].y + aHL[mt][nt].y + aLH[mt][nt].y;
                c.z = aHH[mt][nt].z + aHL[mt][nt].z + aLH[mt][nt].z;
                c.w = aHH[mt][nt].w + aHL[mt][nt].w + aLH[mt][nt].w;
                const int colr = mt * 16 + (lane >> 2);
                const int bcol = (wn * 2 + nt) * 8 + (lane & 3) * 2;
                *(float2*)&slab[colr * 66 + bcol] = make_float2(c.x, c.y);
                *(float2*)&slab[(colr + 8) * 66 + bcol] = make_float2(c.z, c.w);
            }
        __syncthreads();

        // pointwise: thread owns batch b_pw, gate cols jj0, jj0+1
        float2 c_old = *(float2*)&cs[b_pw * 8 + jj0];
        float co[2] = {c_old.x, c_old.y};
        float gf[2] = {pf.x, pf.y}, gi2[2] = {pi.x, pi.y};
        float gg2[2] = {pg.x, pg.y}, go[2] = {po.x, po.y};
        float hv[2], cv[2];
#pragma unroll
        for (int j = 0; j < 2; j++) {
            const int jj = jj0 + j;
            float xf = gt[jj * 66 + b_pw]        + gt[GT_GRP + jj * 66 + b_pw]        + gf[j];
            float xi = gt[(8 + jj) * 66 + b_pw]  + gt[GT_GRP + (8 + jj) * 66 + b_pw]  + gi2[j];
            float xg = gt[(16 + jj) * 66 + b_pw] + gt[GT_GRP + (16 + jj) * 66 + b_pw] + gg2[j];
            float xo = gt[(24 + jj) * 66 + b_pw] + gt[GT_GRP + (24 + jj) * 66 + b_pw] + go[j];
            float f = sigmoidf_(xf), ig = sigmoidf_(xi);
            float gv = tanhf(xg),    o  = sigmoidf_(xo);
            cv[j] = f * co[j] + ig * gv;
            hv[j] = o * tanhf(cv[j]);
        }
        *(float2*)&cs[b_pw * 8 + jj0] = make_float2(cv[0], cv[1]);
        // write h as fp32 (layer out) and pre-split bf16 (next step operand)
        uint2 hs = bsplit(make_float2(hv[0], hv[1]));
        *(uint*)&wHi[b_pw * 1024 + jb * 8 + jj0] = hs.x;
        *(uint*)&wLo[b_pw * 1024 + jb * 8 + jj0] = hs.y;
        *(float2*)&layer_out[((size_t)b_pw * T_ + t) * H_ + jb * 8 + jj0] =
            make_float2(hv[0], hv[1]);
        if (t == T_ - 1) {
            size_t hb2 = (size_t)B_ * T_ * H_ + (size_t)l * B_ * H_ +
                         (size_t)b_pw * H_ + jb * 8 + jj0;
            *(float2*)&outp[hb2] = make_float2(hv[0], hv[1]);
            *(float2*)&outp[hb2 + (size_t)L_ * B_ * H_] = make_float2(cv[0], cv[1]);
        }
    }
}

extern "C" void kernel_launch(void* const* d_in, const int* in_sizes, int n_in,
                              void* d_out, int out_size)
{
    const float* x  = (const float*)d_in[0];
    const float* W  = (const float*)d_in[1];
    const float* bs = (const float*)d_in[2];
    const float* h0 = (const float*)d_in[3];
    const float* c0 = (const float*)d_in[4];
    float* out = (float*)d_out;

    float *gin, *mid;
    ushort* hbf;
    cudaGetSymbolAddress((void**)&gin, g_gin);
    cudaGetSymbolAddress((void**)&mid, g_mid);
    cudaGetSymbolAddress((void**)&hbf, g_hbf);
    ushort* hHi0 = hbf;
    ushort* hLo0 = hbf + B_ * H_;
    ushort* hHi1 = hbf + 2 * B_ * H_;
    ushort* hLo1 = hbf + 3 * B_ * H_;

    cudaFuncSetAttribute(lstm_seq, cudaFuncAttributeMaxDynamicSharedMemorySize,
                         SM_BYTES);

    for (int l = 0; l < L_; l++) {
        const float* layer_in  = (l == 0) ? x   : mid;
        float*       layer_out = (l == 0) ? mid : out;
        const float* Wl = W  + (size_t)l * G_ * K2_;
        const float* bl = bs + (size_t)l * G_;

        lstm_in_gemm<<<dim3(64, 256), 256>>>(layer_in, Wl, bl, gin);
        lstm_seq<<<NBLK, 256, SM_BYTES>>>(Wl, gin,
                                          c0 + (size_t)l * B_ * H_,
                                          h0 + (size_t)l * B_ * H_,
                                          hHi0, hLo0, hHi1, hLo1,
                                          layer_out, out, l);
    }
}